// round 2
// baseline (speedup 1.0000x reference)
#include <cuda_runtime.h>
#include <cstdint>

// Problem constants
#define BB   2
#define CH   128
#define HWN  4096          // H*W = N tokens
#define NTOK 4096
#define BNC  8192          // BB * NTOK
#define CC   256           // 2*CH (real plane then imag plane)
#define NN   (4096ull*4096ull)
#define EPSV 1e-5f
#define SCALE_QK 0.08838834764831845f   // C^-0.5 = 1/sqrt(128)

// ---------------- scratch (device globals; no allocation allowed) ----------
__device__ float g_x   [(size_t)CC * BNC];        // normalized planar (2C, B*N)   8 MB
__device__ float g_qkv [(size_t)3 * CC * BNC];    // rows: 0..255 Q, 256..511 K, 512..767 V  24 MB
__device__ float g_vt  [(size_t)BB * NTOK * CC];  // V transposed (B,N,2C)         8 MB
__device__ float g_attn[(size_t)BB * NN];         // attention matrix              128 MB
__device__ float g_o   [(size_t)BB * NTOK * CC];  // attention output (B,N,2C)     8 MB
__device__ float g_ws  [3 * CC * CC];             // stacked weights (768 x 256)
__device__ float g_bs  [3 * CC];
__device__ float g_scale[CC];
__device__ float g_shift[CC];

// ---------------- 1. BN statistics: one block per (comp,channel) -----------
__global__ void bn_stats_kernel(const float* __restrict__ x,
                                const float* __restrict__ bn_w,
                                const float* __restrict__ bn_b) {
    int cc = blockIdx.x;                 // 0..255 ; cc = comp*CH + c
    int comp = cc / CH, c = cc % CH;
    float s1 = 0.f, s2 = 0.f;
    for (int i = threadIdx.x; i < BB * HWN; i += blockDim.x) {
        int b = i / HWN, n = i - b * HWN;
        float v = x[(((size_t)(b * CH + c)) * HWN + n) * 2 + comp];
        s1 += v; s2 += v * v;
    }
    __shared__ float sh1[256], sh2[256];
    sh1[threadIdx.x] = s1; sh2[threadIdx.x] = s2;
    __syncthreads();
    for (int s = 128; s > 0; s >>= 1) {
        if (threadIdx.x < s) { sh1[threadIdx.x] += sh1[threadIdx.x + s];
                               sh2[threadIdx.x] += sh2[threadIdx.x + s]; }
        __syncthreads();
    }
    if (threadIdx.x == 0) {
        const float inv = 1.f / (float)(BB * HWN);
        float mean = sh1[0] * inv;
        float var  = sh2[0] * inv - mean * mean;
        float sc   = bn_w[c * 2 + comp] * rsqrtf(var + EPSV);
        g_scale[cc] = sc;
        g_shift[cc] = bn_b[c * 2 + comp] - mean * sc;
    }
}

// ---------------- 2. normalize + planarize ---------------------------------
__global__ void normalize_kernel(const float* __restrict__ x) {
    int idx = blockIdx.x * blockDim.x + threadIdx.x;   // over BB*CH*HWN
    if (idx >= BB * CH * HWN) return;
    int n = idx % HWN;
    int c = (idx / HWN) % CH;
    int b = idx / (CH * HWN);
    float2 v = ((const float2*)x)[idx];                // (real, imag)
    size_t col = (size_t)b * NTOK + n;
    g_x[(size_t)c * BNC + col]        = v.x * g_scale[c]      + g_shift[c];
    g_x[(size_t)(CH + c) * BNC + col] = v.y * g_scale[CH + c] + g_shift[CH + c];
}

// ---------------- 3. build stacked complex weights -------------------------
__global__ void stack_w_kernel(const float* __restrict__ wq, const float* __restrict__ bq,
                               const float* __restrict__ wk, const float* __restrict__ bk,
                               const float* __restrict__ wv, const float* __restrict__ bv) {
    int idx = blockIdx.x * blockDim.x + threadIdx.x;   // over 3*CH*CH
    if (idx >= 3 * CH * CH) return;
    int p = idx / (CH * CH);
    int r = idx - p * (CH * CH);
    int o = r / CH, i = r % CH;
    const float* w = (p == 0) ? wq : ((p == 1) ? wk : wv);
    float wr = w[(o * CH + i) * 2 + 0];
    float wi = w[(o * CH + i) * 2 + 1];
    float* ws = g_ws + (size_t)p * CC * CC;
    ws[o * CC + i]             =  wr;
    ws[o * CC + CH + i]        = -wi;
    ws[(CH + o) * CC + i]      =  wi;
    ws[(CH + o) * CC + CH + i] =  wr;
    if (i == 0) {
        const float* bbp = (p == 0) ? bq : ((p == 1) ? bk : bv);
        g_bs[p * CC + o]      = bbp[o * 2 + 0];
        g_bs[p * CC + CH + o] = bbp[o * 2 + 1];
    }
}

// ---------------- 4. QKV projection GEMM: (768x256) x (256x8192) -----------
__global__ __launch_bounds__(256) void proj_gemm_kernel() {
    __shared__ float As[16][129];   // padded: transposed store, conflict-free
    __shared__ float Bs[16][128];
    int row0 = blockIdx.y * 128;
    int col0 = blockIdx.x * 128;
    int t = threadIdx.x;
    int ti = t >> 4, tj = t & 15;
    float acc[8][8];
    #pragma unroll
    for (int r = 0; r < 8; r++)
        #pragma unroll
        for (int c = 0; c < 8; c++) acc[r][c] = 0.f;

    for (int k0 = 0; k0 < CC; k0 += 16) {
        #pragma unroll
        for (int s = 0; s < 8; s++) {          // A: 128 rows x 16 k
            int l = t + s * 256;
            int i = l >> 4, kk = l & 15;
            As[kk][i] = g_ws[(size_t)(row0 + i) * CC + k0 + kk];
        }
        #pragma unroll
        for (int s = 0; s < 8; s++) {          // B: 16 k x 128 cols (coalesced)
            int l = t + s * 256;
            int kk = l >> 7, j = l & 127;
            Bs[kk][j] = g_x[(size_t)(k0 + kk) * BNC + col0 + j];
        }
        __syncthreads();
        #pragma unroll
        for (int kk = 0; kk < 16; kk++) {
            float a[8], bv[8];
            #pragma unroll
            for (int r = 0; r < 8; r++) a[r] = As[kk][ti * 8 + r];
            float4 b0 = *(const float4*)&Bs[kk][tj * 8];
            float4 b1 = *(const float4*)&Bs[kk][tj * 8 + 4];
            bv[0]=b0.x; bv[1]=b0.y; bv[2]=b0.z; bv[3]=b0.w;
            bv[4]=b1.x; bv[5]=b1.y; bv[6]=b1.z; bv[7]=b1.w;
            #pragma unroll
            for (int r = 0; r < 8; r++)
                #pragma unroll
                for (int c = 0; c < 8; c++) acc[r][c] += a[r] * bv[c];
        }
        __syncthreads();
    }
    #pragma unroll
    for (int r = 0; r < 8; r++) {
        int row = row0 + ti * 8 + r;
        float bias = g_bs[row];
        float4 o0 = make_float4(acc[r][0]+bias, acc[r][1]+bias, acc[r][2]+bias, acc[r][3]+bias);
        float4 o1 = make_float4(acc[r][4]+bias, acc[r][5]+bias, acc[r][6]+bias, acc[r][7]+bias);
        *(float4*)&g_qkv[(size_t)row * BNC + col0 + tj * 8]     = o0;
        *(float4*)&g_qkv[(size_t)row * BNC + col0 + tj * 8 + 4] = o1;
    }
}

// ---------------- 5. logits GEMM: L = scale * (Q^T K) over 256 planes ------
__global__ __launch_bounds__(256) void logits_gemm_kernel() {
    __shared__ float As[16][128];
    __shared__ float Bs[16][128];
    int bz = blockIdx.z;
    int n0 = blockIdx.y * 128;
    int m0 = blockIdx.x * 128;
    size_t colQ = (size_t)bz * NTOK + n0;
    size_t colK = (size_t)bz * NTOK + m0;
    const float* Q = g_qkv;                    // rows 0..255
    const float* K = g_qkv + (size_t)CC * BNC; // rows 256..511
    int t = threadIdx.x;
    int ti = t >> 4, tj = t & 15;
    float acc[8][8];
    #pragma unroll
    for (int r = 0; r < 8; r++)
        #pragma unroll
        for (int c = 0; c < 8; c++) acc[r][c] = 0.f;

    for (int k0 = 0; k0 < CC; k0 += 16) {
        #pragma unroll
        for (int s = 0; s < 8; s++) {
            int l = t + s * 256;
            int kk = l >> 7, j = l & 127;
            As[kk][j] = Q[(size_t)(k0 + kk) * BNC + colQ + j];
            Bs[kk][j] = K[(size_t)(k0 + kk) * BNC + colK + j];
        }
        __syncthreads();
        #pragma unroll
        for (int kk = 0; kk < 16; kk++) {
            float4 a0 = *(const float4*)&As[kk][ti * 8];
            float4 a1 = *(const float4*)&As[kk][ti * 8 + 4];
            float4 b0 = *(const float4*)&Bs[kk][tj * 8];
            float4 b1 = *(const float4*)&Bs[kk][tj * 8 + 4];
            float a[8] = {a0.x,a0.y,a0.z,a0.w,a1.x,a1.y,a1.z,a1.w};
            float bv[8] = {b0.x,b0.y,b0.z,b0.w,b1.x,b1.y,b1.z,b1.w};
            #pragma unroll
            for (int r = 0; r < 8; r++)
                #pragma unroll
                for (int c = 0; c < 8; c++) acc[r][c] += a[r] * bv[c];
        }
        __syncthreads();
    }
    float* L = g_attn + (size_t)bz * NN;
    #pragma unroll
    for (int r = 0; r < 8; r++) {
        size_t row = (size_t)(n0 + ti * 8 + r) * NTOK + m0 + tj * 8;
        float4 o0 = make_float4(acc[r][0]*SCALE_QK, acc[r][1]*SCALE_QK,
                                acc[r][2]*SCALE_QK, acc[r][3]*SCALE_QK);
        float4 o1 = make_float4(acc[r][4]*SCALE_QK, acc[r][5]*SCALE_QK,
                                acc[r][6]*SCALE_QK, acc[r][7]*SCALE_QK);
        *(float4*)&L[row]     = o0;
        *(float4*)&L[row + 4] = o1;
    }
}

// ---------------- 6. softmax rows (in place) --------------------------------
__global__ __launch_bounds__(256) void softmax_kernel() {
    size_t rid = blockIdx.x;                  // 0..8191
    float* row = g_attn + rid * NTOK;
    int t = threadIdx.x;
    float v[16];
    float mx = -1e30f;
    #pragma unroll
    for (int k = 0; k < 16; k++) {
        v[k] = row[t + k * 256];
        mx = fmaxf(mx, v[k]);
    }
    __shared__ float sh[256];
    sh[t] = mx; __syncthreads();
    for (int s = 128; s > 0; s >>= 1) {
        if (t < s) sh[t] = fmaxf(sh[t], sh[t + s]);
        __syncthreads();
    }
    mx = sh[0]; __syncthreads();
    float sum = 0.f;
    #pragma unroll
    for (int k = 0; k < 16; k++) { v[k] = __expf(v[k] - mx); sum += v[k]; }
    sh[t] = sum; __syncthreads();
    for (int s = 128; s > 0; s >>= 1) {
        if (t < s) sh[t] += sh[t + s];
        __syncthreads();
    }
    float inv = 1.f / sh[0];
    #pragma unroll
    for (int k = 0; k < 16; k++) row[t + k * 256] = v[k] * inv;
}

// ---------------- 7. transpose V: (2C, B*N) -> (B*N, 2C) -------------------
__global__ void transpose_v_kernel() {
    __shared__ float sh[32][33];
    const float* V = g_qkv + (size_t)2 * CC * BNC;   // rows 512..767
    int m0 = blockIdx.x * 32;        // column index into (2C,B*N)
    int c0 = blockIdx.y * 32;        // row index (cc)
    int tx = threadIdx.x, ty = threadIdx.y;
    sh[ty][tx] = V[(size_t)(c0 + ty) * BNC + m0 + tx];
    __syncthreads();
    g_vt[(size_t)(m0 + ty) * CC + c0 + tx] = sh[tx][ty];
}

// ---------------- 8. output GEMM: O = attn @ Vt  (N x 2C, K = N) -----------
__global__ __launch_bounds__(256) void out_gemm_kernel() {
    __shared__ float As[16][65];     // padded transpose store
    __shared__ float Bs[16][128];
    int bz = blockIdx.z;
    int n0 = blockIdx.y * 64;
    int c0 = blockIdx.x * 128;
    const float* A = g_attn + (size_t)bz * NN;
    const float* Bv = g_vt + (size_t)bz * NTOK * CC;
    int t = threadIdx.x;
    int ti = t >> 4, tj = t & 15;
    float acc[4][8];
    #pragma unroll
    for (int r = 0; r < 4; r++)
        #pragma unroll
        for (int c = 0; c < 8; c++) acc[r][c] = 0.f;

    for (int k0 = 0; k0 < NTOK; k0 += 16) {
        #pragma unroll
        for (int s = 0; s < 4; s++) {          // A: 64 rows x 16 k
            int l = t + s * 256;
            int i = l >> 4, kk = l & 15;
            As[kk][i] = A[(size_t)(n0 + i) * NTOK + k0 + kk];
        }
        #pragma unroll
        for (int s = 0; s < 8; s++) {          // B: 16 k x 128 cc (coalesced)
            int l = t + s * 256;
            int kk = l >> 7, j = l & 127;
            Bs[kk][j] = Bv[(size_t)(k0 + kk) * CC + c0 + j];
        }
        __syncthreads();
        #pragma unroll
        for (int kk = 0; kk < 16; kk++) {
            float a[4];
            #pragma unroll
            for (int r = 0; r < 4; r++) a[r] = As[kk][ti * 4 + r];
            float4 b0 = *(const float4*)&Bs[kk][tj * 8];
            float4 b1 = *(const float4*)&Bs[kk][tj * 8 + 4];
            float bv[8] = {b0.x,b0.y,b0.z,b0.w,b1.x,b1.y,b1.z,b1.w};
            #pragma unroll
            for (int r = 0; r < 4; r++)
                #pragma unroll
                for (int c = 0; c < 8; c++) acc[r][c] += a[r] * bv[c];
        }
        __syncthreads();
    }
    #pragma unroll
    for (int r = 0; r < 4; r++) {
        size_t row = ((size_t)bz * NTOK + n0 + ti * 4 + r) * CC + c0 + tj * 8;
        *(float4*)&g_o[row]     = make_float4(acc[r][0],acc[r][1],acc[r][2],acc[r][3]);
        *(float4*)&g_o[row + 4] = make_float4(acc[r][4],acc[r][5],acc[r][6],acc[r][7]);
    }
}

// ---------------- 9. residual add (vs NORMALIZED x!) + interleave back ------
// Reference: xn = BN(x); return xn + gamma*out.  Residual base is xn, which
// lives planar in g_x (2C, B*N).
__global__ void final_add_kernel(const float* __restrict__ gamma_p,
                                 float* __restrict__ out) {
    __shared__ float shr[32][33];
    __shared__ float shi[32][33];
    float gamma = *gamma_p;
    int b  = blockIdx.z;
    int c0 = blockIdx.y * 32;
    int n0 = blockIdx.x * 32;
    int tx = threadIdx.x, ty = threadIdx.y;
    // read O coalesced over cc
    size_t obase = ((size_t)b * NTOK + n0 + ty) * CC;
    shr[ty][tx] = g_o[obase + c0 + tx];
    shi[ty][tx] = g_o[obase + CH + c0 + tx];
    __syncthreads();
    // write out coalesced over n (float2 = (real,imag))
    int c = c0 + ty;
    int n = n0 + tx;
    size_t col = (size_t)b * NTOK + n;
    float xr = g_x[(size_t)c * BNC + col];          // normalized real
    float xi = g_x[(size_t)(CH + c) * BNC + col];   // normalized imag
    size_t oi = (size_t)(b * CH + c) * HWN + n;
    float2 ov;
    ov.x = xr + gamma * shr[tx][ty];
    ov.y = xi + gamma * shi[tx][ty];
    ((float2*)out)[oi] = ov;
}

// ---------------- launch -----------------------------------------------------
extern "C" void kernel_launch(void* const* d_in, const int* in_sizes, int n_in,
                              void* d_out, int out_size) {
    const float* x    = (const float*)d_in[0];
    const float* bn_w = (const float*)d_in[1];
    const float* bn_b = (const float*)d_in[2];
    const float* wq   = (const float*)d_in[3];
    const float* bq   = (const float*)d_in[4];
    const float* wk   = (const float*)d_in[5];
    const float* bk   = (const float*)d_in[6];
    const float* wv   = (const float*)d_in[7];
    const float* bv   = (const float*)d_in[8];
    const float* gam  = (const float*)d_in[9];
    float* out = (float*)d_out;

    bn_stats_kernel<<<256, 256>>>(x, bn_w, bn_b);
    normalize_kernel<<<(BB * CH * HWN) / 256, 256>>>(x);
    stack_w_kernel<<<(3 * CH * CH + 255) / 256, 256>>>(wq, bq, wk, bk, wv, bv);
    proj_gemm_kernel<<<dim3(BNC / 128, (3 * CC) / 128), 256>>>();
    logits_gemm_kernel<<<dim3(NTOK / 128, NTOK / 128, BB), 256>>>();
    softmax_kernel<<<BB * NTOK, 256>>>();
    transpose_v_kernel<<<dim3(BNC / 32, CC / 32), dim3(32, 32)>>>();
    out_gemm_kernel<<<dim3(CC / 128, NTOK / 64, BB), 256>>>();
    final_add_kernel<<<dim3(HWN / 32, CH / 32, BB), dim3(32, 32)>>>(gam, out);
}

// round 4
// speedup vs baseline: 5.2880x; 5.2880x over previous
#include <cuda_runtime.h>
#include <cuda_bf16.h>
#include <cstdint>

// Problem constants
#define BB   2
#define CH   128
#define HWN  4096
#define NTOK 4096
#define BNC  8192          // BB * NTOK
#define CC   256           // 2*CH (real plane then imag plane)
#define NN   (4096ull*4096ull)
#define EPSV 1e-5f
#define SCALE_QK 0.08838834764831845f   // 1/sqrt(128)

typedef __nv_bfloat16 bf16;

// ---------------- scratch (device globals) ---------------------------------
__device__ __align__(256) float g_x   [(size_t)CC * BNC];   // normalized planar fp32 (2C, B*N)
__device__ __align__(256) bf16  g_xt  [(size_t)BNC * CC];   // normalized token-major bf16
__device__ __align__(256) bf16  g_qt  [(size_t)BNC * CC];   // Q token-major bf16
__device__ __align__(256) bf16  g_kt  [(size_t)BNC * CC];   // K token-major bf16
__device__ __align__(256) bf16  g_vp  [(size_t)CC * BNC];   // V planar bf16 (cc, B*N)
__device__ __align__(256) float g_attn[(size_t)BB * NN];    // logits fp32 / attn bf16 in-place
__device__ __align__(256) float g_o   [(size_t)BB * NTOK * CC]; // attention out (B,N,2C) fp32
__device__ __align__(256) bf16  g_ws_bf[3 * CC * CC];       // stacked complex weights bf16
__device__ float g_bs  [3 * CC];
__device__ float g_scale[CC];
__device__ float g_shift[CC];

// ---------------- PTX helpers (base-ISA only: sm_80-class) ------------------
__device__ __forceinline__ uint32_t smem_u32(const void* p) {
    uint32_t a;
    asm("{ .reg .u64 t; cvta.to.shared.u64 t, %1; cvt.u32.u64 %0, t; }" : "=r"(a) : "l"(p));
    return a;
}
__device__ __forceinline__ void cpa16(uint32_t dst, const void* src) {
    asm volatile("cp.async.cg.shared.global [%0], [%1], 16;" :: "r"(dst), "l"(src) : "memory");
}
#define CP_COMMIT() asm volatile("cp.async.commit_group;" ::: "memory")
#define CP_WAIT(n)  asm volatile("cp.async.wait_group %0;" :: "n"(n) : "memory")

#define LDMX4(r, addr) \
    asm volatile("ldmatrix.sync.aligned.m8n8.x4.shared.b16 {%0,%1,%2,%3}, [%4];" \
        : "=r"((r)[0]), "=r"((r)[1]), "=r"((r)[2]), "=r"((r)[3]) : "r"(addr))

#define MMA16816(d, a, b0v, b1v) \
    asm volatile("mma.sync.aligned.m16n8k16.row.col.f32.bf16.bf16.f32 " \
        "{%0,%1,%2,%3}, {%4,%5,%6,%7}, {%8,%9}, {%0,%1,%2,%3};" \
        : "+f"((d)[0]), "+f"((d)[1]), "+f"((d)[2]), "+f"((d)[3]) \
        : "r"((a)[0]), "r"((a)[1]), "r"((a)[2]), "r"((a)[3]), "r"(b0v), "r"(b1v))

// SMEM tile geometry: 128 rows x 32 bf16 (64B data) padded to 80B/row
#define ROWB  80
#define TILEB (128 * ROWB)

// ---------------- unified HMMA GEMM: D(128x128) = A(128xK) . B(128xK)^T ----
// EPI 0: proj  (grid 64 x 6)        A=g_xt,      B=g_ws_bf,  K=256
// EPI 1: logit (grid 32 x 32 x 2)   A=g_qt,      B=g_kt,     K=256
// EPI 2: out   (grid 32 x 2  x 2)   A=attn bf16, B=g_vp,     K=4096
template <int EPI>
__global__ __launch_bounds__(256, 2) void gemm_kernel() {
    __shared__ __align__(16) char sA[2][TILEB];
    __shared__ __align__(16) char sB[2][TILEB];
    const int tid = threadIdx.x, lane = tid & 31, wid = tid >> 5;
    const int bx = blockIdx.x, by = blockIdx.y, bz = blockIdx.z;

    const bf16 *Ap, *Bp; size_t lda, ldb; int nk;
    if (EPI == 0) {
        Ap = g_xt + (size_t)bx * 128 * CC;                 lda = CC;
        Bp = g_ws_bf + (size_t)by * 128 * CC;              ldb = CC;   nk = 8;
    } else if (EPI == 1) {
        Ap = g_qt + ((size_t)bz * NTOK + bx * 128) * CC;   lda = CC;
        Bp = g_kt + ((size_t)bz * NTOK + by * 128) * CC;   ldb = CC;   nk = 8;
    } else {
        Ap = (const bf16*)g_attn + ((size_t)bz * NTOK + bx * 128) * 8192;  lda = 8192;
        Bp = g_vp + (size_t)(by * 128) * BNC + (size_t)bz * NTOK;          ldb = BNC;  nk = 128;
    }

    const uint32_t sa0 = smem_u32(sA[0]), sb0 = smem_u32(sB[0]);

    // loader: one 128x32 bf16 tile of A and of B into buffer (i&1)
    auto load_tile = [&](int i) {
        const int kk0 = i * 32;
        const uint32_t ab = sa0 + (i & 1) * TILEB;
        const uint32_t bb = sb0 + (i & 1) * TILEB;
        #pragma unroll
        for (int it = 0; it < 2; it++) {
            int l = tid + it * 256;          // 512 chunks of 16B
            int row = l >> 2, kc = l & 3;
            cpa16(ab + row * ROWB + kc * 16, Ap + (size_t)row * lda + kk0 + kc * 8);
            cpa16(bb + row * ROWB + kc * 16, Bp + (size_t)row * ldb + kk0 + kc * 8);
        }
    };

    float acc[2][8][4];
    #pragma unroll
    for (int mt = 0; mt < 2; mt++)
        #pragma unroll
        for (int nj = 0; nj < 8; nj++)
            #pragma unroll
            for (int e = 0; e < 4; e++) acc[mt][nj][e] = 0.f;

    const int m0  = (wid & 3) * 32;     // warp M offset (4 warps along M)
    const int n0w = (wid >> 2) * 64;    // warp N offset (2 warps along N)

    load_tile(0); CP_COMMIT();

    for (int i = 0; i < nk; i++) {
        if (i + 1 < nk) { load_tile(i + 1); CP_COMMIT(); CP_WAIT(1); }
        else           { CP_WAIT(0); }
        __syncthreads();

        const uint32_t aB = sa0 + (i & 1) * TILEB;
        const uint32_t bB = sb0 + (i & 1) * TILEB;
        #pragma unroll
        for (int ks = 0; ks < 32; ks += 16) {
            uint32_t af[2][4], bfr[4][4];
            #pragma unroll
            for (int mt = 0; mt < 2; mt++) {
                uint32_t addr = aB + (m0 + mt * 16 + (lane & 15)) * ROWB
                              + (ks + ((lane >> 4) << 3)) * 2;
                LDMX4(af[mt], addr);
            }
            #pragma unroll
            for (int nt = 0; nt < 4; nt++) {
                uint32_t addr = bB + (n0w + nt * 16 + (lane & 7) + ((lane & 16) >> 1)) * ROWB
                              + (ks + (((lane >> 3) & 1) << 3)) * 2;
                LDMX4(bfr[nt], addr);
            }
            #pragma unroll
            for (int mt = 0; mt < 2; mt++)
                #pragma unroll
                for (int nt = 0; nt < 4; nt++) {
                    MMA16816(acc[mt][2 * nt],     af[mt], bfr[nt][0], bfr[nt][1]);
                    MMA16816(acc[mt][2 * nt + 1], af[mt], bfr[nt][2], bfr[nt][3]);
                }
        }
        __syncthreads();
    }

    // ---- epilogue: d0,d1 -> (row, c),(row, c+1); d2,d3 -> (row+8, ...) -----
    const int r_base = bx * 128 + m0 + (lane >> 2);
    const int c_loc0 = n0w + (lane & 3) * 2;

    #pragma unroll
    for (int mt = 0; mt < 2; mt++) {
        #pragma unroll
        for (int nj = 0; nj < 8; nj++) {
            float* d = acc[mt][nj];
            const int r0 = r_base + mt * 16;       // token row (global for EPI0)
            const int c  = c_loc0 + nj * 8;        // local N col 0..127

            if (EPI == 0) {
                int gc = by * 128 + c;             // stacked output channel 0..767
                float bi0 = g_bs[gc], bi1 = g_bs[gc + 1];
                if (gc < 512) {                    // Q or K: token-major bf16
                    bf16* dst = (gc < 256) ? g_qt : g_kt;
                    int cc = gc & 255;
                    __nv_bfloat162 v0 = __float22bfloat162_rn(make_float2(d[0] + bi0, d[1] + bi1));
                    __nv_bfloat162 v1 = __float22bfloat162_rn(make_float2(d[2] + bi0, d[3] + bi1));
                    *(__nv_bfloat162*)&dst[(size_t)r0 * CC + cc]       = v0;
                    *(__nv_bfloat162*)&dst[(size_t)(r0 + 8) * CC + cc] = v1;
                } else {                           // V: planar bf16 (cc, B*N)
                    int cc = gc - 512;
                    g_vp[(size_t)cc * BNC + r0]             = __float2bfloat16(d[0] + bi0);
                    g_vp[(size_t)(cc + 1) * BNC + r0]       = __float2bfloat16(d[1] + bi1);
                    g_vp[(size_t)cc * BNC + r0 + 8]         = __float2bfloat16(d[2] + bi0);
                    g_vp[(size_t)(cc + 1) * BNC + r0 + 8]   = __float2bfloat16(d[3] + bi1);
                }
            } else if (EPI == 1) {
                float* L = g_attn + (size_t)bz * NN;
                size_t col = (size_t)by * 128 + c;
                float2 v0 = make_float2(d[0] * SCALE_QK, d[1] * SCALE_QK);
                float2 v1 = make_float2(d[2] * SCALE_QK, d[3] * SCALE_QK);
                *(float2*)&L[(size_t)r0 * NTOK + col]       = v0;
                *(float2*)&L[(size_t)(r0 + 8) * NTOK + col] = v1;
            } else {
                int cc = by * 128 + c;
                float* O = g_o + (size_t)bz * NTOK * CC;
                *(float2*)&O[(size_t)r0 * CC + cc]       = make_float2(d[0], d[1]);
                *(float2*)&O[(size_t)(r0 + 8) * CC + cc] = make_float2(d[2], d[3]);
            }
        }
    }
}

// ---------------- BN statistics ---------------------------------------------
__global__ void bn_stats_kernel(const float* __restrict__ x,
                                const float* __restrict__ bn_w,
                                const float* __restrict__ bn_b) {
    int cc = blockIdx.x;
    int comp = cc / CH, c = cc % CH;
    float s1 = 0.f, s2 = 0.f;
    for (int i = threadIdx.x; i < BB * HWN; i += blockDim.x) {
        int b = i / HWN, n = i - b * HWN;
        float v = x[(((size_t)(b * CH + c)) * HWN + n) * 2 + comp];
        s1 += v; s2 += v * v;
    }
    __shared__ float sh1[256], sh2[256];
    sh1[threadIdx.x] = s1; sh2[threadIdx.x] = s2;
    __syncthreads();
    for (int s = 128; s > 0; s >>= 1) {
        if (threadIdx.x < s) { sh1[threadIdx.x] += sh1[threadIdx.x + s];
                               sh2[threadIdx.x] += sh2[threadIdx.x + s]; }
        __syncthreads();
    }
    if (threadIdx.x == 0) {
        const float inv = 1.f / (float)(BB * HWN);
        float mean = sh1[0] * inv;
        float var  = sh2[0] * inv - mean * mean;
        float sc   = bn_w[c * 2 + comp] * rsqrtf(var + EPSV);
        g_scale[cc] = sc;
        g_shift[cc] = bn_b[c * 2 + comp] - mean * sc;
    }
}

// ---------------- normalize: planar fp32 + token-major bf16 -----------------
__global__ void normalize_kernel(const float* __restrict__ x) {
    __shared__ float shr[32][33];
    __shared__ float shi[32][33];
    int b  = blockIdx.z;
    int c0 = blockIdx.y * 32;
    int n0 = blockIdx.x * 32;
    int tx = threadIdx.x, ty = threadIdx.y;
    int c = c0 + ty, n = n0 + tx;
    float2 v = ((const float2*)x)[(size_t)(b * CH + c) * HWN + n];
    float xr = v.x * g_scale[c]      + g_shift[c];
    float xi = v.y * g_scale[CH + c] + g_shift[CH + c];
    size_t col = (size_t)b * NTOK + n;
    g_x[(size_t)c * BNC + col]        = xr;
    g_x[(size_t)(CH + c) * BNC + col] = xi;
    shr[ty][tx] = xr; shi[ty][tx] = xi;
    __syncthreads();
    int token = n0 + ty, cw = c0 + tx;
    bf16* dst = g_xt + ((size_t)b * NTOK + token) * CC;
    dst[cw]      = __float2bfloat16(shr[tx][ty]);
    dst[CH + cw] = __float2bfloat16(shi[tx][ty]);
}

// ---------------- stacked complex weights (bf16) ----------------------------
__global__ void stack_w_kernel(const float* __restrict__ wq, const float* __restrict__ bq,
                               const float* __restrict__ wk, const float* __restrict__ bk,
                               const float* __restrict__ wv, const float* __restrict__ bv) {
    int idx = blockIdx.x * blockDim.x + threadIdx.x;
    if (idx >= 3 * CH * CH) return;
    int p = idx / (CH * CH);
    int r = idx - p * (CH * CH);
    int o = r / CH, i = r % CH;
    const float* w = (p == 0) ? wq : ((p == 1) ? wk : wv);
    float wr = w[(o * CH + i) * 2 + 0];
    float wi = w[(o * CH + i) * 2 + 1];
    bf16* ws = g_ws_bf + (size_t)p * CC * CC;
    ws[o * CC + i]             = __float2bfloat16( wr);
    ws[o * CC + CH + i]        = __float2bfloat16(-wi);
    ws[(CH + o) * CC + i]      = __float2bfloat16( wi);
    ws[(CH + o) * CC + CH + i] = __float2bfloat16( wr);
    if (i == 0) {
        const float* bbp = (p == 0) ? bq : ((p == 1) ? bk : bv);
        g_bs[p * CC + o]      = bbp[o * 2 + 0];
        g_bs[p * CC + CH + o] = bbp[o * 2 + 1];
    }
}

// ---------------- softmax (fp32 in, bf16 out in place) ----------------------
__global__ __launch_bounds__(256) void softmax_kernel() {
    size_t rid = blockIdx.x;
    float* row = g_attn + rid * NTOK;
    int t = threadIdx.x;
    float v[16];
    float mx = -1e30f;
    #pragma unroll
    for (int k = 0; k < 16; k++) {
        v[k] = row[t + k * 256];
        mx = fmaxf(mx, v[k]);
    }
    __shared__ float sh[256];
    sh[t] = mx; __syncthreads();
    for (int s = 128; s > 0; s >>= 1) {
        if (t < s) sh[t] = fmaxf(sh[t], sh[t + s]);
        __syncthreads();
    }
    mx = sh[0]; __syncthreads();
    float sum = 0.f;
    #pragma unroll
    for (int k = 0; k < 16; k++) { v[k] = __expf(v[k] - mx); sum += v[k]; }
    sh[t] = sum; __syncthreads();
    for (int s = 128; s > 0; s >>= 1) {
        if (t < s) sh[t] += sh[t + s];
        __syncthreads();
    }
    float inv = 1.f / sh[0];
    bf16* brow = (bf16*)row;
    #pragma unroll
    for (int k = 0; k < 16; k++) brow[t + k * 256] = __float2bfloat16(v[k] * inv);
}

// ---------------- residual add (vs normalized xn) + interleave --------------
__global__ void final_add_kernel(const float* __restrict__ gamma_p,
                                 float* __restrict__ out) {
    __shared__ float shr[32][33];
    __shared__ float shi[32][33];
    float gamma = *gamma_p;
    int b  = blockIdx.z;
    int c0 = blockIdx.y * 32;
    int n0 = blockIdx.x * 32;
    int tx = threadIdx.x, ty = threadIdx.y;
    size_t obase = ((size_t)b * NTOK + n0 + ty) * CC;
    shr[ty][tx] = g_o[obase + c0 + tx];
    shi[ty][tx] = g_o[obase + CH + c0 + tx];
    __syncthreads();
    int c = c0 + ty;
    int n = n0 + tx;
    size_t col = (size_t)b * NTOK + n;
    float xr = g_x[(size_t)c * BNC + col];
    float xi = g_x[(size_t)(CH + c) * BNC + col];
    size_t oi = (size_t)(b * CH + c) * HWN + n;
    float2 ov;
    ov.x = xr + gamma * shr[tx][ty];
    ov.y = xi + gamma * shi[tx][ty];
    ((float2*)out)[oi] = ov;
}

// ---------------- launch -----------------------------------------------------
extern "C" void kernel_launch(void* const* d_in, const int* in_sizes, int n_in,
                              void* d_out, int out_size) {
    const float* x    = (const float*)d_in[0];
    const float* bn_w = (const float*)d_in[1];
    const float* bn_b = (const float*)d_in[2];
    const float* wq   = (const float*)d_in[3];
    const float* bq   = (const float*)d_in[4];
    const float* wk   = (const float*)d_in[5];
    const float* bk   = (const float*)d_in[6];
    const float* wv   = (const float*)d_in[7];
    const float* bv   = (const float*)d_in[8];
    const float* gam  = (const float*)d_in[9];
    float* out = (float*)d_out;

    bn_stats_kernel<<<256, 256>>>(x, bn_w, bn_b);
    normalize_kernel<<<dim3(HWN / 32, CH / 32, BB), dim3(32, 32)>>>(x);
    stack_w_kernel<<<(3 * CH * CH + 255) / 256, 256>>>(wq, bq, wk, bk, wv, bv);
    gemm_kernel<0><<<dim3(BNC / 128, 6), 256>>>();
    gemm_kernel<1><<<dim3(NTOK / 128, NTOK / 128, BB), 256>>>();
    softmax_kernel<<<BB * NTOK, 256>>>();
    gemm_kernel<2><<<dim3(NTOK / 128, CC / 128, BB), 256>>>();
    final_add_kernel<<<dim3(HWN / 32, CH / 32, BB), dim3(32, 32)>>>(gam, out);
}

// round 5
// speedup vs baseline: 6.6214x; 1.2522x over previous
#include <cuda_runtime.h>
#include <cuda_bf16.h>
#include <cuda_fp16.h>
#include <cstdint>

// Problem constants
#define BB   2
#define CH   128
#define HWN  4096
#define NTOK 4096
#define BNC  8192          // BB * NTOK
#define CC   256           // 2*CH (real plane then imag plane)
#define NN   (4096ull*4096ull)
#define EPSV 1e-5f
#define SCALE_QK 0.08838834764831845f   // 1/sqrt(128)

typedef __nv_bfloat16 bf16;

// ---------------- scratch (device globals) ---------------------------------
__device__ __align__(256) float  g_x   [(size_t)CC * BNC];   // normalized planar fp32 (2C, B*N)
__device__ __align__(256) bf16   g_xt  [(size_t)BNC * CC];   // normalized token-major bf16
__device__ __align__(256) bf16   g_qt  [(size_t)BNC * CC];   // Q token-major bf16
__device__ __align__(256) bf16   g_kt  [(size_t)BNC * CC];   // K token-major bf16
__device__ __align__(256) bf16   g_vp  [(size_t)CC * BNC];   // V planar bf16 (cc, B*N)
__device__ __align__(256) __half g_attn[(size_t)BB * NN];    // logits fp16 / attn bf16 in-place (64MB)
__device__ __align__(256) float  g_o   [(size_t)BB * NTOK * CC]; // attention out (B,N,2C) fp32
__device__ __align__(256) bf16   g_ws_bf[3 * CC * CC];       // stacked complex weights bf16
__device__ float g_bs  [3 * CC];
__device__ float g_scale[CC];
__device__ float g_shift[CC];

// ---------------- PTX helpers (base-ISA only) --------------------------------
__device__ __forceinline__ uint32_t smem_u32(const void* p) {
    uint32_t a;
    asm("{ .reg .u64 t; cvta.to.shared.u64 t, %1; cvt.u32.u64 %0, t; }" : "=r"(a) : "l"(p));
    return a;
}
__device__ __forceinline__ void cpa16(uint32_t dst, const void* src) {
    asm volatile("cp.async.cg.shared.global [%0], [%1], 16;" :: "r"(dst), "l"(src) : "memory");
}
#define CP_COMMIT() asm volatile("cp.async.commit_group;" ::: "memory")
#define CP_WAIT(n)  asm volatile("cp.async.wait_group %0;" :: "n"(n) : "memory")

#define LDMX4(r, addr) \
    asm volatile("ldmatrix.sync.aligned.m8n8.x4.shared.b16 {%0,%1,%2,%3}, [%4];" \
        : "=r"((r)[0]), "=r"((r)[1]), "=r"((r)[2]), "=r"((r)[3]) : "r"(addr))

#define MMA16816(d, a, b0v, b1v) \
    asm volatile("mma.sync.aligned.m16n8k16.row.col.f32.bf16.bf16.f32 " \
        "{%0,%1,%2,%3}, {%4,%5,%6,%7}, {%8,%9}, {%0,%1,%2,%3};" \
        : "+f"((d)[0]), "+f"((d)[1]), "+f"((d)[2]), "+f"((d)[3]) \
        : "r"((a)[0]), "r"((a)[1]), "r"((a)[2]), "r"((a)[3]), "r"(b0v), "r"(b1v))

// SMEM tile geometry: 128 rows x 64 bf16 (128B data) padded to 144B/row.
// 144 = 128+16 -> 8 consecutive rows hit 8 distinct 16B bank groups (conflict-free ldmatrix).
#define ROWB   144
#define TILEB  (128 * ROWB)          // 18432 B
#define STAGES 3
#define SM_TOTAL (2 * STAGES * TILEB) // 110592 B

// ---------------- unified HMMA GEMM: D(128x128) = A(128xK) . B(128xK)^T ----
// EPI 0: proj  (grid 64 x 6)        A=g_xt,      B=g_ws_bf,  K=256
// EPI 1: logit (grid 32 x 32 x 2)   A=g_qt,      B=g_kt,     K=256  (fp16 out)
// EPI 2: out   (grid 32 x 2  x 2)   A=attn bf16, B=g_vp,     K=4096
template <int EPI>
__global__ __launch_bounds__(256, 2) void gemm_kernel() {
    extern __shared__ __align__(16) char smem[];
    const int tid = threadIdx.x, lane = tid & 31, wid = tid >> 5;
    const int bx = blockIdx.x, by = blockIdx.y, bz = blockIdx.z;

    const bf16 *Ap, *Bp; size_t lda, ldb; int nk;
    if (EPI == 0) {
        Ap = g_xt + (size_t)bx * 128 * CC;                 lda = CC;
        Bp = g_ws_bf + (size_t)by * 128 * CC;              ldb = CC;   nk = 4;
    } else if (EPI == 1) {
        Ap = g_qt + ((size_t)bz * NTOK + bx * 128) * CC;   lda = CC;
        Bp = g_kt + ((size_t)bz * NTOK + by * 128) * CC;   ldb = CC;   nk = 4;
    } else {
        Ap = (const bf16*)g_attn + ((size_t)bz * NTOK + bx * 128) * NTOK; lda = NTOK;
        Bp = g_vp + (size_t)(by * 128) * BNC + (size_t)bz * NTOK;         ldb = BNC;  nk = 64;
    }

    const uint32_t sa0 = smem_u32(smem);
    const uint32_t sb0 = sa0 + STAGES * TILEB;

    // loader: one 128x64 bf16 tile of A and of B into stage (i % STAGES)
    auto load_tile = [&](int i) {
        const int kk0 = i * 64;
        const int st = i % STAGES;
        const uint32_t ab = sa0 + st * TILEB;
        const uint32_t bb = sb0 + st * TILEB;
        #pragma unroll
        for (int it = 0; it < 4; it++) {
            int l = tid + it * 256;          // 1024 chunks of 16B per tile
            int row = l >> 3, kc = l & 7;
            cpa16(ab + row * ROWB + kc * 16, Ap + (size_t)row * lda + kk0 + kc * 8);
            cpa16(bb + row * ROWB + kc * 16, Bp + (size_t)row * ldb + kk0 + kc * 8);
        }
    };

    float acc[2][8][4];
    #pragma unroll
    for (int mt = 0; mt < 2; mt++)
        #pragma unroll
        for (int nj = 0; nj < 8; nj++)
            #pragma unroll
            for (int e = 0; e < 4; e++) acc[mt][nj][e] = 0.f;

    const int m0  = (wid & 3) * 32;     // warp M offset (4 warps along M)
    const int n0w = (wid >> 2) * 64;    // warp N offset (2 warps along N)

    load_tile(0); CP_COMMIT();
    if (nk > 1) { load_tile(1); CP_COMMIT(); }

    for (int i = 0; i < nk; i++) {
        if (i + 2 < nk) { load_tile(i + 2); CP_COMMIT(); CP_WAIT(2); }
        else if (i + 1 < nk) { CP_WAIT(1); }
        else { CP_WAIT(0); }
        __syncthreads();

        const int st = i % STAGES;
        const uint32_t aB = sa0 + st * TILEB;
        const uint32_t bB = sb0 + st * TILEB;
        #pragma unroll
        for (int ks = 0; ks < 64; ks += 16) {
            uint32_t af[2][4], bfr[4][4];
            #pragma unroll
            for (int mt = 0; mt < 2; mt++) {
                uint32_t addr = aB + (m0 + mt * 16 + (lane & 15)) * ROWB
                              + (ks + ((lane >> 4) << 3)) * 2;
                LDMX4(af[mt], addr);
            }
            #pragma unroll
            for (int nt = 0; nt < 4; nt++) {
                uint32_t addr = bB + (n0w + nt * 16 + (lane & 7) + ((lane & 16) >> 1)) * ROWB
                              + (ks + (((lane >> 3) & 1) << 3)) * 2;
                LDMX4(bfr[nt], addr);
            }
            #pragma unroll
            for (int mt = 0; mt < 2; mt++)
                #pragma unroll
                for (int nt = 0; nt < 4; nt++) {
                    MMA16816(acc[mt][2 * nt],     af[mt], bfr[nt][0], bfr[nt][1]);
                    MMA16816(acc[mt][2 * nt + 1], af[mt], bfr[nt][2], bfr[nt][3]);
                }
        }
        __syncthreads();   // protect stage buffer from next iteration's prefetch
    }

    // ---- epilogue: d0,d1 -> (row, c),(row, c+1); d2,d3 -> (row+8, ...) -----
    const int r_base = bx * 128 + m0 + (lane >> 2);
    const int c_loc0 = n0w + (lane & 3) * 2;

    #pragma unroll
    for (int mt = 0; mt < 2; mt++) {
        #pragma unroll
        for (int nj = 0; nj < 8; nj++) {
            float* d = acc[mt][nj];
            const int r0 = r_base + mt * 16;
            const int c  = c_loc0 + nj * 8;

            if (EPI == 0) {
                int gc = by * 128 + c;             // stacked output channel 0..767
                float bi0 = g_bs[gc], bi1 = g_bs[gc + 1];
                if (gc < 512) {                    // Q or K: token-major bf16
                    bf16* dst = (gc < 256) ? g_qt : g_kt;
                    int cc = gc & 255;
                    __nv_bfloat162 v0 = __float22bfloat162_rn(make_float2(d[0] + bi0, d[1] + bi1));
                    __nv_bfloat162 v1 = __float22bfloat162_rn(make_float2(d[2] + bi0, d[3] + bi1));
                    *(__nv_bfloat162*)&dst[(size_t)r0 * CC + cc]       = v0;
                    *(__nv_bfloat162*)&dst[(size_t)(r0 + 8) * CC + cc] = v1;
                } else {                           // V: planar bf16 (cc, B*N)
                    int cc = gc - 512;
                    g_vp[(size_t)cc * BNC + r0]             = __float2bfloat16(d[0] + bi0);
                    g_vp[(size_t)(cc + 1) * BNC + r0]       = __float2bfloat16(d[1] + bi1);
                    g_vp[(size_t)cc * BNC + r0 + 8]         = __float2bfloat16(d[2] + bi0);
                    g_vp[(size_t)(cc + 1) * BNC + r0 + 8]   = __float2bfloat16(d[3] + bi1);
                }
            } else if (EPI == 1) {
                __half* L = g_attn + (size_t)bz * NN;
                size_t col = (size_t)by * 128 + c;
                __half2 v0 = __floats2half2_rn(d[0] * SCALE_QK, d[1] * SCALE_QK);
                __half2 v1 = __floats2half2_rn(d[2] * SCALE_QK, d[3] * SCALE_QK);
                *(__half2*)&L[(size_t)r0 * NTOK + col]       = v0;
                *(__half2*)&L[(size_t)(r0 + 8) * NTOK + col] = v1;
            } else {
                int cc = by * 128 + c;
                float* O = g_o + (size_t)bz * NTOK * CC;
                *(float2*)&O[(size_t)r0 * CC + cc]       = make_float2(d[0], d[1]);
                *(float2*)&O[(size_t)(r0 + 8) * CC + cc] = make_float2(d[2], d[3]);
            }
        }
    }
}

// ---------------- BN statistics ---------------------------------------------
__global__ void bn_stats_kernel(const float* __restrict__ x,
                                const float* __restrict__ bn_w,
                                const float* __restrict__ bn_b) {
    int cc = blockIdx.x;
    int comp = cc / CH, c = cc % CH;
    float s1 = 0.f, s2 = 0.f;
    for (int i = threadIdx.x; i < BB * HWN; i += blockDim.x) {
        int b = i / HWN, n = i - b * HWN;
        float v = x[(((size_t)(b * CH + c)) * HWN + n) * 2 + comp];
        s1 += v; s2 += v * v;
    }
    __shared__ float sh1[256], sh2[256];
    sh1[threadIdx.x] = s1; sh2[threadIdx.x] = s2;
    __syncthreads();
    for (int s = 128; s > 0; s >>= 1) {
        if (threadIdx.x < s) { sh1[threadIdx.x] += sh1[threadIdx.x + s];
                               sh2[threadIdx.x] += sh2[threadIdx.x + s]; }
        __syncthreads();
    }
    if (threadIdx.x == 0) {
        const float inv = 1.f / (float)(BB * HWN);
        float mean = sh1[0] * inv;
        float var  = sh2[0] * inv - mean * mean;
        float sc   = bn_w[c * 2 + comp] * rsqrtf(var + EPSV);
        g_scale[cc] = sc;
        g_shift[cc] = bn_b[c * 2 + comp] - mean * sc;
    }
}

// ---------------- normalize: planar fp32 + token-major bf16 -----------------
__global__ void normalize_kernel(const float* __restrict__ x) {
    __shared__ float shr[32][33];
    __shared__ float shi[32][33];
    int b  = blockIdx.z;
    int c0 = blockIdx.y * 32;
    int n0 = blockIdx.x * 32;
    int tx = threadIdx.x, ty = threadIdx.y;
    int c = c0 + ty, n = n0 + tx;
    float2 v = ((const float2*)x)[(size_t)(b * CH + c) * HWN + n];
    float xr = v.x * g_scale[c]      + g_shift[c];
    float xi = v.y * g_scale[CH + c] + g_shift[CH + c];
    size_t col = (size_t)b * NTOK + n;
    g_x[(size_t)c * BNC + col]        = xr;
    g_x[(size_t)(CH + c) * BNC + col] = xi;
    shr[ty][tx] = xr; shi[ty][tx] = xi;
    __syncthreads();
    int token = n0 + ty, cw = c0 + tx;
    bf16* dst = g_xt + ((size_t)b * NTOK + token) * CC;
    dst[cw]      = __float2bfloat16(shr[tx][ty]);
    dst[CH + cw] = __float2bfloat16(shi[tx][ty]);
}

// ---------------- stacked complex weights (bf16) ----------------------------
__global__ void stack_w_kernel(const float* __restrict__ wq, const float* __restrict__ bq,
                               const float* __restrict__ wk, const float* __restrict__ bk,
                               const float* __restrict__ wv, const float* __restrict__ bv) {
    int idx = blockIdx.x * blockDim.x + threadIdx.x;
    if (idx >= 3 * CH * CH) return;
    int p = idx / (CH * CH);
    int r = idx - p * (CH * CH);
    int o = r / CH, i = r % CH;
    const float* w = (p == 0) ? wq : ((p == 1) ? wk : wv);
    float wr = w[(o * CH + i) * 2 + 0];
    float wi = w[(o * CH + i) * 2 + 1];
    bf16* ws = g_ws_bf + (size_t)p * CC * CC;
    ws[o * CC + i]             = __float2bfloat16( wr);
    ws[o * CC + CH + i]        = __float2bfloat16(-wi);
    ws[(CH + o) * CC + i]      = __float2bfloat16( wi);
    ws[(CH + o) * CC + CH + i] = __float2bfloat16( wr);
    if (i == 0) {
        const float* bbp = (p == 0) ? bq : ((p == 1) ? bk : bv);
        g_bs[p * CC + o]      = bbp[o * 2 + 0];
        g_bs[p * CC + CH + o] = bbp[o * 2 + 1];
    }
}

// ---------------- softmax (fp16 in, bf16 out in place) ----------------------
__global__ __launch_bounds__(256) void softmax_kernel() {
    size_t rid = blockIdx.x;
    __half2* row2 = (__half2*)(g_attn + rid * NTOK);       // 2048 half2
    int t = threadIdx.x;
    float2 v[8];
    float mx = -1e30f;
    #pragma unroll
    for (int k = 0; k < 8; k++) {
        v[k] = __half22float2(row2[t + k * 256]);
        mx = fmaxf(mx, fmaxf(v[k].x, v[k].y));
    }
    __shared__ float sh[256];
    sh[t] = mx; __syncthreads();
    for (int s = 128; s > 0; s >>= 1) {
        if (t < s) sh[t] = fmaxf(sh[t], sh[t + s]);
        __syncthreads();
    }
    mx = sh[0]; __syncthreads();
    float sum = 0.f;
    #pragma unroll
    for (int k = 0; k < 8; k++) {
        v[k].x = __expf(v[k].x - mx); v[k].y = __expf(v[k].y - mx);
        sum += v[k].x + v[k].y;
    }
    sh[t] = sum; __syncthreads();
    for (int s = 128; s > 0; s >>= 1) {
        if (t < s) sh[t] += sh[t + s];
        __syncthreads();
    }
    float inv = 1.f / sh[0];
    __nv_bfloat162* brow = (__nv_bfloat162*)(g_attn + rid * NTOK);
    #pragma unroll
    for (int k = 0; k < 8; k++)
        brow[t + k * 256] = __float22bfloat162_rn(make_float2(v[k].x * inv, v[k].y * inv));
}

// ---------------- residual add (vs normalized xn) + interleave --------------
__global__ void final_add_kernel(const float* __restrict__ gamma_p,
                                 float* __restrict__ out) {
    __shared__ float shr[32][33];
    __shared__ float shi[32][33];
    float gamma = *gamma_p;
    int b  = blockIdx.z;
    int c0 = blockIdx.y * 32;
    int n0 = blockIdx.x * 32;
    int tx = threadIdx.x, ty = threadIdx.y;
    size_t obase = ((size_t)b * NTOK + n0 + ty) * CC;
    shr[ty][tx] = g_o[obase + c0 + tx];
    shi[ty][tx] = g_o[obase + CH + c0 + tx];
    __syncthreads();
    int c = c0 + ty;
    int n = n0 + tx;
    size_t col = (size_t)b * NTOK + n;
    float xr = g_x[(size_t)c * BNC + col];
    float xi = g_x[(size_t)(CH + c) * BNC + col];
    size_t oi = (size_t)(b * CH + c) * HWN + n;
    float2 ov;
    ov.x = xr + gamma * shr[tx][ty];
    ov.y = xi + gamma * shi[tx][ty];
    ((float2*)out)[oi] = ov;
}

// ---------------- launch -----------------------------------------------------
extern "C" void kernel_launch(void* const* d_in, const int* in_sizes, int n_in,
                              void* d_out, int out_size) {
    const float* x    = (const float*)d_in[0];
    const float* bn_w = (const float*)d_in[1];
    const float* bn_b = (const float*)d_in[2];
    const float* wq   = (const float*)d_in[3];
    const float* bq   = (const float*)d_in[4];
    const float* wk   = (const float*)d_in[5];
    const float* bk   = (const float*)d_in[6];
    const float* wv   = (const float*)d_in[7];
    const float* bv   = (const float*)d_in[8];
    const float* gam  = (const float*)d_in[9];
    float* out = (float*)d_out;

    static int attr_set = 0;
    if (!attr_set) {
        cudaFuncSetAttribute(gemm_kernel<0>, cudaFuncAttributeMaxDynamicSharedMemorySize, SM_TOTAL);
        cudaFuncSetAttribute(gemm_kernel<1>, cudaFuncAttributeMaxDynamicSharedMemorySize, SM_TOTAL);
        cudaFuncSetAttribute(gemm_kernel<2>, cudaFuncAttributeMaxDynamicSharedMemorySize, SM_TOTAL);
        attr_set = 1;
    }

    bn_stats_kernel<<<256, 256>>>(x, bn_w, bn_b);
    normalize_kernel<<<dim3(HWN / 32, CH / 32, BB), dim3(32, 32)>>>(x);
    stack_w_kernel<<<(3 * CH * CH + 255) / 256, 256>>>(wq, bq, wk, bk, wv, bv);
    gemm_kernel<0><<<dim3(BNC / 128, 6), 256, SM_TOTAL>>>();
    gemm_kernel<1><<<dim3(NTOK / 128, NTOK / 128, BB), 256, SM_TOTAL>>>();
    softmax_kernel<<<BB * NTOK, 256>>>();
    gemm_kernel<2><<<dim3(NTOK / 128, CC / 128, BB), 256, SM_TOTAL>>>();
    final_add_kernel<<<dim3(HWN / 32, CH / 32, BB), dim3(32, 32)>>>(gam, out);
}

// round 6
// speedup vs baseline: 7.2368x; 1.0930x over previous
#include <cuda_runtime.h>
#include <cuda_bf16.h>
#include <cuda_fp16.h>
#include <cstdint>

// Problem constants
#define BB   2
#define CH   128
#define HWN  4096
#define NTOK 4096
#define BNC  8192          // BB * NTOK
#define CC   256           // 2*CH (real plane then imag plane)
#define NN   (4096ull*4096ull)
#define EPSV 1e-5f
#define SCALE_QK 0.08838834764831845f   // 1/sqrt(128)

typedef __nv_bfloat16 bf16;

// ---------------- scratch (device globals) ---------------------------------
__device__ __align__(256) float  g_x   [(size_t)CC * BNC];   // normalized planar fp32 (2C, B*N)
__device__ __align__(256) bf16   g_xt  [(size_t)BNC * CC];   // normalized token-major bf16
__device__ __align__(256) bf16   g_qt  [(size_t)BNC * CC];   // Q token-major bf16 (pre-scaled)
__device__ __align__(256) bf16   g_kt  [(size_t)BNC * CC];   // K token-major bf16
__device__ __align__(256) bf16   g_vp  [(size_t)CC * BNC];   // V planar bf16 (cc, B*N)
__device__ __align__(256) __half g_attn[(size_t)BB * NN];    // logits fp16 / attn bf16 in-place (64MB)
__device__ __align__(256) float  g_o   [(size_t)BB * NTOK * CC]; // partial out, K-half 0
__device__ __align__(256) float  g_o2  [(size_t)BB * NTOK * CC]; // partial out, K-half 1
__device__ __align__(256) bf16   g_ws_bf[3 * CC * CC];       // stacked complex weights bf16
__device__ float g_bs  [3 * CC];
__device__ float g_scale[CC];
__device__ float g_shift[CC];

// ---------------- PTX helpers (base-ISA only) --------------------------------
__device__ __forceinline__ uint32_t smem_u32(const void* p) {
    uint32_t a;
    asm("{ .reg .u64 t; cvta.to.shared.u64 t, %1; cvt.u32.u64 %0, t; }" : "=r"(a) : "l"(p));
    return a;
}
__device__ __forceinline__ void cpa16(uint32_t dst, const void* src) {
    asm volatile("cp.async.cg.shared.global [%0], [%1], 16;" :: "r"(dst), "l"(src) : "memory");
}
#define CP_COMMIT() asm volatile("cp.async.commit_group;" ::: "memory")
#define CP_WAIT(n)  asm volatile("cp.async.wait_group %0;" :: "n"(n) : "memory")

#define LDMX4(r, addr) \
    asm volatile("ldmatrix.sync.aligned.m8n8.x4.shared.b16 {%0,%1,%2,%3}, [%4];" \
        : "=r"((r)[0]), "=r"((r)[1]), "=r"((r)[2]), "=r"((r)[3]) : "r"(addr))

#define MMA16816(d, a, b0v, b1v) \
    asm volatile("mma.sync.aligned.m16n8k16.row.col.f32.bf16.bf16.f32 " \
        "{%0,%1,%2,%3}, {%4,%5,%6,%7}, {%8,%9}, {%0,%1,%2,%3};" \
        : "+f"((d)[0]), "+f"((d)[1]), "+f"((d)[2]), "+f"((d)[3]) \
        : "r"((a)[0]), "r"((a)[1]), "r"((a)[2]), "r"((a)[3]), "r"(b0v), "r"(b1v))

// SMEM tile geometry: 128 rows x 64 bf16 (128B data) padded to 144B/row.
#define ROWB   144
#define TILEB  (128 * ROWB)          // 18432 B
#define STAGES 3
#define SM_TOTAL (2 * STAGES * TILEB) // 110592 B

// ---------------- unified HMMA GEMM: D(128x128) = A(128xK) . B(128xK)^T ----
// EPI 0: proj  (grid 64 x 6)          A=g_xt,      B=g_ws_bf,  K=256
// EPI 1: logit (grid 32 x 32 x 2)     A=g_qt,      B=g_kt,     K=256  (fp16 out)
// EPI 2: out   (grid 32 x 2 x 4)      A=attn bf16, B=g_vp,     K=2048 (split-K=2)
template <int EPI>
__global__ __launch_bounds__(256, 2) void gemm_kernel() {
    extern __shared__ __align__(16) char smem[];
    const int tid = threadIdx.x, lane = tid & 31, wid = tid >> 5;
    const int bx = blockIdx.x, by = blockIdx.y, bz = blockIdx.z;

    const bf16 *Ap, *Bp; size_t lda, ldb; int nk;
    if (EPI == 0) {
        Ap = g_xt + (size_t)bx * 128 * CC;                 lda = CC;
        Bp = g_ws_bf + (size_t)by * 128 * CC;              ldb = CC;   nk = 4;
    } else if (EPI == 1) {
        Ap = g_qt + ((size_t)bz * NTOK + bx * 128) * CC;   lda = CC;
        Bp = g_kt + ((size_t)bz * NTOK + by * 128) * CC;   ldb = CC;   nk = 4;
    } else {
        const int b = bz >> 1, ks = bz & 1;
        Ap = (const bf16*)g_attn + ((size_t)b * NTOK + bx * 128) * NTOK + ks * 2048;
        lda = NTOK;
        Bp = g_vp + (size_t)(by * 128) * BNC + (size_t)b * NTOK + ks * 2048;
        ldb = BNC;  nk = 32;
    }

    const uint32_t sa0 = smem_u32(smem);
    const uint32_t sb0 = sa0 + STAGES * TILEB;

    auto load_tile = [&](int i) {
        const int kk0 = i * 64;
        const int st = i % STAGES;
        const uint32_t ab = sa0 + st * TILEB;
        const uint32_t bb = sb0 + st * TILEB;
        #pragma unroll
        for (int it = 0; it < 4; it++) {
            int l = tid + it * 256;
            int row = l >> 3, kc = l & 7;
            cpa16(ab + row * ROWB + kc * 16, Ap + (size_t)row * lda + kk0 + kc * 8);
            cpa16(bb + row * ROWB + kc * 16, Bp + (size_t)row * ldb + kk0 + kc * 8);
        }
    };

    float acc[2][8][4];
    #pragma unroll
    for (int mt = 0; mt < 2; mt++)
        #pragma unroll
        for (int nj = 0; nj < 8; nj++)
            #pragma unroll
            for (int e = 0; e < 4; e++) acc[mt][nj][e] = 0.f;

    const int m0  = (wid & 3) * 32;
    const int n0w = (wid >> 2) * 64;

    load_tile(0); CP_COMMIT();
    load_tile(1); CP_COMMIT();

    for (int i = 0; i < nk; i++) {
        if (i + 2 < nk) { load_tile(i + 2); CP_COMMIT(); CP_WAIT(2); }
        else if (i + 1 < nk) { CP_WAIT(1); }
        else { CP_WAIT(0); }
        __syncthreads();

        const int st = i % STAGES;
        const uint32_t aB = sa0 + st * TILEB;
        const uint32_t bB = sb0 + st * TILEB;
        #pragma unroll
        for (int ks = 0; ks < 64; ks += 16) {
            uint32_t af[2][4], bfr[4][4];
            #pragma unroll
            for (int mt = 0; mt < 2; mt++) {
                uint32_t addr = aB + (m0 + mt * 16 + (lane & 15)) * ROWB
                              + (ks + ((lane >> 4) << 3)) * 2;
                LDMX4(af[mt], addr);
            }
            #pragma unroll
            for (int nt = 0; nt < 4; nt++) {
                uint32_t addr = bB + (n0w + nt * 16 + (lane & 7) + ((lane & 16) >> 1)) * ROWB
                              + (ks + (((lane >> 3) & 1) << 3)) * 2;
                LDMX4(bfr[nt], addr);
            }
            #pragma unroll
            for (int mt = 0; mt < 2; mt++)
                #pragma unroll
                for (int nt = 0; nt < 4; nt++) {
                    MMA16816(acc[mt][2 * nt],     af[mt], bfr[nt][0], bfr[nt][1]);
                    MMA16816(acc[mt][2 * nt + 1], af[mt], bfr[nt][2], bfr[nt][3]);
                }
        }
        __syncthreads();
    }

    // ---- epilogue ----
    const int r_base = bx * 128 + m0 + (lane >> 2);
    const int c_loc0 = n0w + (lane & 3) * 2;

    #pragma unroll
    for (int mt = 0; mt < 2; mt++) {
        #pragma unroll
        for (int nj = 0; nj < 8; nj++) {
            float* d = acc[mt][nj];
            const int r0 = r_base + mt * 16;
            const int c  = c_loc0 + nj * 8;

            if (EPI == 0) {
                int gc = by * 128 + c;
                float bi0 = g_bs[gc], bi1 = g_bs[gc + 1];
                if (gc < 256) {                    // Q: pre-scale by SCALE_QK
                    bf16* dst = g_qt;
                    __nv_bfloat162 v0 = __float22bfloat162_rn(
                        make_float2((d[0] + bi0) * SCALE_QK, (d[1] + bi1) * SCALE_QK));
                    __nv_bfloat162 v1 = __float22bfloat162_rn(
                        make_float2((d[2] + bi0) * SCALE_QK, (d[3] + bi1) * SCALE_QK));
                    *(__nv_bfloat162*)&dst[(size_t)r0 * CC + gc]       = v0;
                    *(__nv_bfloat162*)&dst[(size_t)(r0 + 8) * CC + gc] = v1;
                } else if (gc < 512) {             // K
                    int cc = gc - 256;
                    __nv_bfloat162 v0 = __float22bfloat162_rn(make_float2(d[0] + bi0, d[1] + bi1));
                    __nv_bfloat162 v1 = __float22bfloat162_rn(make_float2(d[2] + bi0, d[3] + bi1));
                    *(__nv_bfloat162*)&g_kt[(size_t)r0 * CC + cc]       = v0;
                    *(__nv_bfloat162*)&g_kt[(size_t)(r0 + 8) * CC + cc] = v1;
                } else {                           // V: planar
                    int cc = gc - 512;
                    g_vp[(size_t)cc * BNC + r0]           = __float2bfloat16(d[0] + bi0);
                    g_vp[(size_t)(cc + 1) * BNC + r0]     = __float2bfloat16(d[1] + bi1);
                    g_vp[(size_t)cc * BNC + r0 + 8]       = __float2bfloat16(d[2] + bi0);
                    g_vp[(size_t)(cc + 1) * BNC + r0 + 8] = __float2bfloat16(d[3] + bi1);
                }
            } else if (EPI == 1) {
                __half* L = g_attn + (size_t)bz * NN;   // scale already folded into Q
                size_t col = (size_t)by * 128 + c;
                __half2 v0 = __floats2half2_rn(d[0], d[1]);
                __half2 v1 = __floats2half2_rn(d[2], d[3]);
                *(__half2*)&L[(size_t)r0 * NTOK + col]       = v0;
                *(__half2*)&L[(size_t)(r0 + 8) * NTOK + col] = v1;
            } else {
                const int b = bz >> 1, ks = bz & 1;
                int cc = by * 128 + c;
                float* O = (ks ? g_o2 : g_o) + (size_t)b * NTOK * CC;
                *(float2*)&O[(size_t)r0 * CC + cc]       = make_float2(d[0], d[1]);
                *(float2*)&O[(size_t)(r0 + 8) * CC + cc] = make_float2(d[2], d[3]);
            }
        }
    }
}

// ---------------- BN statistics: one block per channel, float4 loads -------
__global__ __launch_bounds__(256) void bn_stats_kernel(const float* __restrict__ x,
                                const float* __restrict__ bn_w,
                                const float* __restrict__ bn_b) {
    int c = blockIdx.x;                 // 0..127
    float sr = 0.f, si = 0.f, qr = 0.f, qi = 0.f;
    #pragma unroll
    for (int b = 0; b < BB; b++) {
        const float4* p = (const float4*)x + (size_t)(b * CH + c) * (HWN / 2);
        for (int i = threadIdx.x; i < HWN / 2; i += 256) {
            float4 v = p[i];                       // (r0,i0,r1,i1)
            sr += v.x + v.z;  si += v.y + v.w;
            qr += v.x * v.x + v.z * v.z;
            qi += v.y * v.y + v.w * v.w;
        }
    }
    #pragma unroll
    for (int o = 16; o > 0; o >>= 1) {
        sr += __shfl_xor_sync(0xFFFFFFFF, sr, o);
        si += __shfl_xor_sync(0xFFFFFFFF, si, o);
        qr += __shfl_xor_sync(0xFFFFFFFF, qr, o);
        qi += __shfl_xor_sync(0xFFFFFFFF, qi, o);
    }
    __shared__ float s4[4][8];
    int wid = threadIdx.x >> 5, lane = threadIdx.x & 31;
    if (lane == 0) { s4[0][wid] = sr; s4[1][wid] = si; s4[2][wid] = qr; s4[3][wid] = qi; }
    __syncthreads();
    if (threadIdx.x == 0) {
        float tsr = 0, tsi = 0, tqr = 0, tqi = 0;
        #pragma unroll
        for (int w = 0; w < 8; w++) { tsr += s4[0][w]; tsi += s4[1][w]; tqr += s4[2][w]; tqi += s4[3][w]; }
        const float inv = 1.f / (float)(BB * HWN);
        float mr = tsr * inv, mi = tsi * inv;
        float vr = tqr * inv - mr * mr, vi = tqi * inv - mi * mi;
        float scr = bn_w[c * 2 + 0] * rsqrtf(vr + EPSV);
        float sci = bn_w[c * 2 + 1] * rsqrtf(vi + EPSV);
        g_scale[c]      = scr;  g_shift[c]      = bn_b[c * 2 + 0] - mr * scr;
        g_scale[CH + c] = sci;  g_shift[CH + c] = bn_b[c * 2 + 1] - mi * sci;
    }
}

// ---------------- normalize: planar fp32 + token-major bf16 -----------------
__global__ void normalize_kernel(const float* __restrict__ x) {
    __shared__ float shr[32][33];
    __shared__ float shi[32][33];
    int b  = blockIdx.z;
    int c0 = blockIdx.y * 32;
    int n0 = blockIdx.x * 32;
    int tx = threadIdx.x, ty = threadIdx.y;
    int c = c0 + ty, n = n0 + tx;
    float2 v = ((const float2*)x)[(size_t)(b * CH + c) * HWN + n];
    float xr = v.x * g_scale[c]      + g_shift[c];
    float xi = v.y * g_scale[CH + c] + g_shift[CH + c];
    size_t col = (size_t)b * NTOK + n;
    g_x[(size_t)c * BNC + col]        = xr;
    g_x[(size_t)(CH + c) * BNC + col] = xi;
    shr[ty][tx] = xr; shi[ty][tx] = xi;
    __syncthreads();
    int token = n0 + ty, cw = c0 + tx;
    bf16* dst = g_xt + ((size_t)b * NTOK + token) * CC;
    dst[cw]      = __float2bfloat16(shr[tx][ty]);
    dst[CH + cw] = __float2bfloat16(shi[tx][ty]);
}

// ---------------- stacked complex weights (bf16) ----------------------------
__global__ void stack_w_kernel(const float* __restrict__ wq, const float* __restrict__ bq,
                               const float* __restrict__ wk, const float* __restrict__ bk,
                               const float* __restrict__ wv, const float* __restrict__ bv) {
    int idx = blockIdx.x * blockDim.x + threadIdx.x;
    if (idx >= 3 * CH * CH) return;
    int p = idx / (CH * CH);
    int r = idx - p * (CH * CH);
    int o = r / CH, i = r % CH;
    const float* w = (p == 0) ? wq : ((p == 1) ? wk : wv);
    float wr = w[(o * CH + i) * 2 + 0];
    float wi = w[(o * CH + i) * 2 + 1];
    bf16* ws = g_ws_bf + (size_t)p * CC * CC;
    ws[o * CC + i]             = __float2bfloat16( wr);
    ws[o * CC + CH + i]        = __float2bfloat16(-wi);
    ws[(CH + o) * CC + i]      = __float2bfloat16( wi);
    ws[(CH + o) * CC + CH + i] = __float2bfloat16( wr);
    if (i == 0) {
        const float* bbp = (p == 0) ? bq : ((p == 1) ? bk : bv);
        g_bs[p * CC + o]      = bbp[o * 2 + 0];
        g_bs[p * CC + CH + o] = bbp[o * 2 + 1];
    }
}

// ---------------- softmax (fp16 in, bf16 out in place, shuffle reductions) --
__global__ __launch_bounds__(256) void softmax_kernel() {
    size_t rid = blockIdx.x;
    __half2* row2 = (__half2*)(g_attn + rid * NTOK);
    int t = threadIdx.x, wid = t >> 5, lane = t & 31;
    __shared__ float sw[8];

    float2 v[8];
    float mx = -1e30f;
    #pragma unroll
    for (int k = 0; k < 8; k++) {
        v[k] = __half22float2(row2[t + k * 256]);
        mx = fmaxf(mx, fmaxf(v[k].x, v[k].y));
    }
    #pragma unroll
    for (int o = 16; o > 0; o >>= 1) mx = fmaxf(mx, __shfl_xor_sync(0xFFFFFFFF, mx, o));
    if (lane == 0) sw[wid] = mx;
    __syncthreads();
    mx = sw[lane & 7];
    #pragma unroll
    for (int o = 4; o > 0; o >>= 1) mx = fmaxf(mx, __shfl_xor_sync(0xFFFFFFFF, mx, o));

    float sum = 0.f;
    #pragma unroll
    for (int k = 0; k < 8; k++) {
        v[k].x = __expf(v[k].x - mx); v[k].y = __expf(v[k].y - mx);
        sum += v[k].x + v[k].y;
    }
    #pragma unroll
    for (int o = 16; o > 0; o >>= 1) sum += __shfl_xor_sync(0xFFFFFFFF, sum, o);
    __syncthreads();            // protect sw reuse
    if (lane == 0) sw[wid] = sum;
    __syncthreads();
    sum = sw[lane & 7];
    #pragma unroll
    for (int o = 4; o > 0; o >>= 1) sum += __shfl_xor_sync(0xFFFFFFFF, sum, o);

    float inv = 1.f / sum;
    __nv_bfloat162* brow = (__nv_bfloat162*)(g_attn + rid * NTOK);
    #pragma unroll
    for (int k = 0; k < 8; k++)
        brow[t + k * 256] = __float22bfloat162_rn(make_float2(v[k].x * inv, v[k].y * inv));
}

// ---------------- residual add (vs normalized xn) + combine split-K ---------
__global__ void final_add_kernel(const float* __restrict__ gamma_p,
                                 float* __restrict__ out) {
    __shared__ float shr[32][33];
    __shared__ float shi[32][33];
    float gamma = *gamma_p;
    int b  = blockIdx.z;
    int c0 = blockIdx.y * 32;
    int n0 = blockIdx.x * 32;
    int tx = threadIdx.x, ty = threadIdx.y;
    size_t obase = ((size_t)b * NTOK + n0 + ty) * CC;
    shr[ty][tx] = g_o[obase + c0 + tx]      + g_o2[obase + c0 + tx];
    shi[ty][tx] = g_o[obase + CH + c0 + tx] + g_o2[obase + CH + c0 + tx];
    __syncthreads();
    int c = c0 + ty;
    int n = n0 + tx;
    size_t col = (size_t)b * NTOK + n;
    float xr = g_x[(size_t)c * BNC + col];
    float xi = g_x[(size_t)(CH + c) * BNC + col];
    size_t oi = (size_t)(b * CH + c) * HWN + n;
    float2 ov;
    ov.x = xr + gamma * shr[tx][ty];
    ov.y = xi + gamma * shi[tx][ty];
    ((float2*)out)[oi] = ov;
}

// ---------------- launch -----------------------------------------------------
extern "C" void kernel_launch(void* const* d_in, const int* in_sizes, int n_in,
                              void* d_out, int out_size) {
    const float* x    = (const float*)d_in[0];
    const float* bn_w = (const float*)d_in[1];
    const float* bn_b = (const float*)d_in[2];
    const float* wq   = (const float*)d_in[3];
    const float* bq   = (const float*)d_in[4];
    const float* wk   = (const float*)d_in[5];
    const float* bk   = (const float*)d_in[6];
    const float* wv   = (const float*)d_in[7];
    const float* bv   = (const float*)d_in[8];
    const float* gam  = (const float*)d_in[9];
    float* out = (float*)d_out;

    static int attr_set = 0;
    if (!attr_set) {
        cudaFuncSetAttribute(gemm_kernel<0>, cudaFuncAttributeMaxDynamicSharedMemorySize, SM_TOTAL);
        cudaFuncSetAttribute(gemm_kernel<1>, cudaFuncAttributeMaxDynamicSharedMemorySize, SM_TOTAL);
        cudaFuncSetAttribute(gemm_kernel<2>, cudaFuncAttributeMaxDynamicSharedMemorySize, SM_TOTAL);
        attr_set = 1;
    }

    bn_stats_kernel<<<CH, 256>>>(x, bn_w, bn_b);
    normalize_kernel<<<dim3(HWN / 32, CH / 32, BB), dim3(32, 32)>>>(x);
    stack_w_kernel<<<(3 * CH * CH + 255) / 256, 256>>>(wq, bq, wk, bk, wv, bv);
    gemm_kernel<0><<<dim3(BNC / 128, 6), 256, SM_TOTAL>>>();
    gemm_kernel<1><<<dim3(NTOK / 128, NTOK / 128, BB), 256, SM_TOTAL>>>();
    softmax_kernel<<<BB * NTOK, 256>>>();
    gemm_kernel<2><<<dim3(NTOK / 128, CC / 128, BB * 2), 256, SM_TOTAL>>>();
    final_add_kernel<<<dim3(HWN / 32, CH / 32, BB), dim3(32, 32)>>>(gam, out);
}